// round 4
// baseline (speedup 1.0000x reference)
#include <cuda_runtime.h>
#include <cuda_bf16.h>

// CenterLoss, B=1024, C=100000, F=128.
// loss = ( sum_b clip(||x_b - centers[labels_b]||^2, 1e-12, 1e12)
//          + (B*C - B)*1e-12 ) / B
// One-hot mask + clip => the [B,C] distmat is never materialized.
//
// Single fused kernel, 16 blocks x 1024 threads:
//   - warp w handles rows base+w and base+32+w (2 rows per warp)
//   - block reduce via smem, one partial per block
//   - "last block reduces" with an acq_rel atomic counter (NO threadfence)
//   - last block sums the 16 partials in fixed order -> deterministic

#define BATCH     1024
#define FEAT      128
#define NB        16
#define TPB       1024
#define ROWS_PER_BLOCK 64
// (B*C - B) * 1e-12 = 1024*99999*1e-12
#define MASK_CONST 1.02398976e-4f
#define INV_BATCH  0.0009765625f   // 1/1024, exact

__device__ float        g_partials[NB];
__device__ unsigned int g_count = 0;   // re-armed to 0 by the last block

__global__ __launch_bounds__(TPB)
void centerloss_fused(const float* __restrict__ x,
                      const int*   __restrict__ labels,
                      const float* __restrict__ centers,
                      float*       __restrict__ out) {
    const int warp = threadIdx.x >> 5;
    const int lane = threadIdx.x & 31;
    const int row0 = blockIdx.x * ROWS_PER_BLOCK + warp;        // rows 0..1023
    const int row1 = row0 + 32;

    // Two rows per warp; each lane one float4 of each 128-dim row.
    const int lbl0 = __ldg(labels + row0);
    const int lbl1 = __ldg(labels + row1);

    const float4* xr0 = reinterpret_cast<const float4*>(x + (size_t)row0 * FEAT);
    const float4* xr1 = reinterpret_cast<const float4*>(x + (size_t)row1 * FEAT);
    const float4* cr0 = reinterpret_cast<const float4*>(centers + (size_t)lbl0 * FEAT);
    const float4* cr1 = reinterpret_cast<const float4*>(centers + (size_t)lbl1 * FEAT);

    float4 a0 = __ldg(xr0 + lane);
    float4 a1 = __ldg(xr1 + lane);
    float4 c0 = __ldg(cr0 + lane);
    float4 c1 = __ldg(cr1 + lane);

    float dx = a0.x - c0.x, dy = a0.y - c0.y, dz = a0.z - c0.z, dw = a0.w - c0.w;
    float d0 = fmaf(dx, dx, fmaf(dy, dy, fmaf(dz, dz, dw * dw)));
    dx = a1.x - c1.x; dy = a1.y - c1.y; dz = a1.z - c1.z; dw = a1.w - c1.w;
    float d1 = fmaf(dx, dx, fmaf(dy, dy, fmaf(dz, dz, dw * dw)));

    // warp tree reduce both rows (fixed order -> deterministic)
    #pragma unroll
    for (int o = 16; o > 0; o >>= 1) {
        d0 += __shfl_xor_sync(0xFFFFFFFFu, d0, o);
        d1 += __shfl_xor_sync(0xFFFFFFFFu, d1, o);
    }

    __shared__ float ws[32];
    if (lane == 0) {
        // clip each row's distance, then combine
        ws[warp] = fminf(fmaxf(d0, 1e-12f), 1e12f)
                 + fminf(fmaxf(d1, 1e-12f), 1e12f);
    }
    __syncthreads();

    if (warp == 0) {
        float v = ws[lane];
        #pragma unroll
        for (int o = 16; o > 0; o >>= 1)
            v += __shfl_xor_sync(0xFFFFFFFFu, v, o);

        if (lane == 0) {
            g_partials[blockIdx.x] = v;
            // Release: order the partial store before the counter bump.
            // Acquire: order the partial loads below after it.
            unsigned int t;
            asm volatile("atom.acq_rel.gpu.global.add.u32 %0, [%1], %2;"
                         : "=r"(t)
                         : "l"(&g_count), "r"(1u)
                         : "memory");
            if (t == NB - 1u) {
                // Last block: sum all 16 partials in fixed order.
                float total = 0.0f;
                #pragma unroll
                for (int b = 0; b < NB; b++) {
                    float p;
                    asm volatile("ld.acquire.gpu.global.f32 %0, [%1];"
                                 : "=f"(p) : "l"(g_partials + b) : "memory");
                    total += p;
                }
                out[0] = (total + MASK_CONST) * INV_BATCH;
                g_count = 0;   // re-arm for the next graph replay
            }
        }
    }
}

extern "C" void kernel_launch(void* const* d_in, const int* in_sizes, int n_in,
                              void* d_out, int out_size) {
    const float* x       = (const float*)d_in[0];   // [1024, 128] f32
    const int*   labels  = (const int*)  d_in[1];   // [1024] i32
    const float* centers = (const float*)d_in[2];   // [100000, 128] f32
    float* out = (float*)d_out;

    centerloss_fused<<<NB, TPB>>>(x, labels, centers, out);
}

// round 5
// speedup vs baseline: 1.5026x; 1.5026x over previous
#include <cuda_runtime.h>
#include <cuda_bf16.h>

// CenterLoss, B=1024, C=100000, F=128.
// loss = ( sum_b clip(||x_b - centers[labels_b]||^2, 1e-12, 1e12)
//          + (B*C - B)*1e-12 ) / B
// One-hot mask + clip => the [B,C] distmat is never materialized.
//
// Two kernels (R3 structure, best so far) + PDL: finalize is launched with
// programmatic-dependent-launch so its setup overlaps kernel 1's execution;
// it griddepcontrol.wait's before touching g_row.

#define BATCH     1024
#define FEAT      128
#define NBLOCKS   128
#define WARPS_PER_BLOCK 8
// (B*C - B) * 1e-12 = 1024*99999*1e-12
#define MASK_CONST 1.02398976e-4f
#define INV_BATCH  0.0009765625f   // 1/1024, exact

__device__ float g_row[BATCH];    // per-row clipped squared distances

__global__ __launch_bounds__(WARPS_PER_BLOCK * 32)
void centerloss_rows(const float* __restrict__ x,
                     const int*   __restrict__ labels,
                     const float* __restrict__ centers) {
    const int warp = threadIdx.x >> 5;
    const int lane = threadIdx.x & 31;
    const int row  = blockIdx.x * WARPS_PER_BLOCK + warp;   // 0..1023

    // One warp per row; each lane one float4 of the 128-dim row.
    const float4* xr = reinterpret_cast<const float4*>(x + (size_t)row * FEAT);
    const int lbl = __ldg(labels + row);
    const float4* cr = reinterpret_cast<const float4*>(centers + (size_t)lbl * FEAT);

    float4 a = __ldg(xr + lane);
    float4 c = __ldg(cr + lane);
    float dx = a.x - c.x, dy = a.y - c.y, dz = a.z - c.z, dw = a.w - c.w;
    float d = fmaf(dx, dx, fmaf(dy, dy, fmaf(dz, dz, dw * dw)));

    // warp tree reduce (fixed order -> deterministic)
    #pragma unroll
    for (int o = 16; o > 0; o >>= 1)
        d += __shfl_xor_sync(0xFFFFFFFFu, d, o);

    if (lane == 0)
        g_row[row] = fminf(fmaxf(d, 1e-12f), 1e12f);   // per-row clip
}

__global__ __launch_bounds__(128)
void centerloss_finalize(float* __restrict__ out) {
    // Block until the primary grid (centerloss_rows) has fully completed.
    // Under a plain (non-PDL) launch this is a no-op.
    asm volatile("griddepcontrol.wait;" ::: "memory");

    const int tid  = threadIdx.x;       // 0..127
    const int lane = tid & 31;
    const int warp = tid >> 5;

    // 128 threads x 8 floats (2 float4) = 1024 row sums
    const float4* p = reinterpret_cast<const float4*>(g_row);
    float4 a = p[tid * 2];
    float4 b = p[tid * 2 + 1];
    float v = ((a.x + a.y) + (a.z + a.w)) + ((b.x + b.y) + (b.z + b.w));

    #pragma unroll
    for (int o = 16; o > 0; o >>= 1)
        v += __shfl_xor_sync(0xFFFFFFFFu, v, o);

    __shared__ float ws[4];
    if (lane == 0) ws[warp] = v;
    __syncthreads();

    if (tid == 0) {
        float total = (ws[0] + ws[1]) + (ws[2] + ws[3]);
        out[0] = (total + MASK_CONST) * INV_BATCH;
    }
}

extern "C" void kernel_launch(void* const* d_in, const int* in_sizes, int n_in,
                              void* d_out, int out_size) {
    const float* x       = (const float*)d_in[0];   // [1024, 128] f32
    const int*   labels  = (const int*)  d_in[1];   // [1024] i32
    const float* centers = (const float*)d_in[2];   // [100000, 128] f32
    float* out = (float*)d_out;

    centerloss_rows<<<NBLOCKS, WARPS_PER_BLOCK * 32>>>(x, labels, centers);

    // Launch finalize with programmatic dependent launch so its setup
    // overlaps centerloss_rows' execution.
    cudaLaunchAttribute attr[1];
    attr[0].id = cudaLaunchAttributeProgrammaticStreamSerialization;
    attr[0].val.programmaticStreamSerializationAllowed = 1;

    cudaLaunchConfig_t cfg = {};
    cfg.gridDim  = dim3(1, 1, 1);
    cfg.blockDim = dim3(128, 1, 1);
    cfg.dynamicSmemBytes = 0;
    cfg.stream = 0;
    cfg.attrs = attr;
    cfg.numAttrs = 1;

    cudaError_t e = cudaLaunchKernelEx(&cfg, centerloss_finalize, out);
    if (e != cudaSuccess) {
        // Fallback: plain serialized launch (griddepcontrol.wait is a no-op).
        cudaGetLastError();   // clear the error
        centerloss_finalize<<<1, 128>>>(out);
    }
}